// round 6
// baseline (speedup 1.0000x reference)
#include <cuda_runtime.h>
#include <cuda_fp16.h>
#include <cstdint>

#define B_    16
#define C_    192
#define HW_   4096
#define NOUT  (C_*C_)
#define KSPLIT 8
#define KPER   (HW_/KSPLIT)     // 512
#define NKT    (KPER/64)        // 8 k-tiles (64 k each = one image row)

__device__ float g_sums[80];
// fp16 copies: variant v: 0 -> dx=-1, 1 -> dx=0, 2 -> dx=+1  (edge-clamped in x)
__device__ __half g_xh[(size_t)3 * B_ * C_ * HW_];

// ---------------------------------------------------------------------------
__device__ __forceinline__ uint32_t smem_u32(const void* p) {
    uint32_t a;
    asm("{ .reg .u64 t; cvta.to.shared.u64 t, %1; cvt.u32.u64 %0, t; }" : "=r"(a) : "l"(p));
    return a;
}
__device__ __forceinline__ void cp_async16(uint32_t dst, const void* src) {
    asm volatile("cp.async.cg.shared.global [%0], [%1], 16;" :: "r"(dst), "l"(src) : "memory");
}
__device__ __forceinline__ void cp_commit() {
    asm volatile("cp.async.commit_group;" ::: "memory");
}
template <int N>
__device__ __forceinline__ void cp_wait() {
    asm volatile("cp.async.wait_group %0;" :: "n"(N) : "memory");
}
__device__ __forceinline__ void ldsm4(uint32_t* r, uint32_t addr) {
    asm volatile("ldmatrix.sync.aligned.m8n8.x4.shared.b16 {%0,%1,%2,%3}, [%4];"
                 : "=r"(r[0]), "=r"(r[1]), "=r"(r[2]), "=r"(r[3]) : "r"(addr));
}
__device__ __forceinline__ void mma16(float* d, const uint32_t* a, const uint32_t* b) {
    asm volatile("mma.sync.aligned.m16n8k16.row.col.f32.f16.f16.f32 "
                 "{%0,%1,%2,%3}, {%4,%5,%6,%7}, {%8,%9}, {%0,%1,%2,%3};"
                 : "+f"(d[0]), "+f"(d[1]), "+f"(d[2]), "+f"(d[3])
                 : "r"(a[0]), "r"(a[1]), "r"(a[2]), "r"(a[3]), "r"(b[0]), "r"(b[1]));
}
__device__ __forceinline__ void red_v4(float* gp, float4 v) {
    asm volatile("red.global.add.v4.f32 [%0], {%1,%2,%3,%4};"
                 :: "l"(gp), "f"(v.x), "f"(v.y), "f"(v.z), "f"(v.w) : "memory");
}

// ---------------------------------------------------------------------------
// prep: fp16-convert x into 3 dx-shifted variants (dy handled at fill time).
// ---------------------------------------------------------------------------
__global__ __launch_bounds__(256) void cofe_prep(const float* __restrict__ x) {
    int idx = blockIdx.x * 256 + threadIdx.x;     // 12288 * 256
    int row = idx >> 4;                            // (b*C + c)*64 + y
    int q   = idx & 15;
    const float* src = x + (size_t)row * 64 + q * 4;
    float4 v = *reinterpret_cast<const float4*>(src);
    float lm = (q == 0)  ? v.x : src[-1];
    float rp = (q == 15) ? v.w : src[4];

    size_t o = (size_t)row * 64 + q * 4;
    const size_t VS = (size_t)B_ * C_ * HW_;
    __half2* d0 = reinterpret_cast<__half2*>(g_xh + o);            // dx=-1
    __half2* d1 = reinterpret_cast<__half2*>(g_xh + VS + o);       // dx=0
    __half2* d2 = reinterpret_cast<__half2*>(g_xh + 2 * VS + o);   // dx=+1
    d0[0] = __floats2half2_rn(lm,  v.x); d0[1] = __floats2half2_rn(v.y, v.z);
    d1[0] = __floats2half2_rn(v.x, v.y); d1[1] = __floats2half2_rn(v.z, v.w);
    d2[0] = __floats2half2_rn(v.y, v.z); d2[1] = __floats2half2_rn(v.w, rp);
}

// ---------------------------------------------------------------------------
// GEMM: CTA tile M=96, N=192, K=512 (one split), fp16 HMMA m16n8k16.
// Epilogue: acc -> smem (contiguous 96x192 tile) -> red.global.add.v4.f32
// ---------------------------------------------------------------------------
#define STAGE_B 36864
#define SM_REQ  (2 * STAGE_B)

__global__ __launch_bounds__(128, 2)
void cofe_mma(float* __restrict__ out) {
    extern __shared__ char smraw[];
    const uint32_t smem = smem_u32(smraw);

    const int tid  = threadIdx.x;
    const int lane = tid & 31;
    const int wid  = tid >> 5;
    const int wr   = wid >> 1;
    const int wc   = wid & 1;

    const int bx  = blockIdx.x;
    const int s   = bx & 7;             // k-split
    const int mt  = (bx >> 3) & 1;      // M tile
    const int g   = bx >> 4;            // 0..79
    const int b   = g / 5, off = g % 5;
    const int dy  = (off < 3) ? -1 : 0;
    const int dx  = (off < 3) ? (off - 1) : ((off == 3) ? -1 : 0);

    const int cA0 = mt * 96;
    const int y0  = s * (KPER / 64);
    const size_t VS = (size_t)B_ * C_ * HW_;
    const __half* xAh = g_xh + VS + ((size_t)(b * C_ + cA0)) * HW_;      // dx=0
    const __half* xBh = g_xh + (size_t)(dx + 1) * VS + (size_t)(b * C_) * HW_;

    const int mrel  = (lane & 7) + ((lane >> 3) & 1) * 8;
    const int kcsA  = lane >> 4;
    const int nrel  = (lane & 7) + (lane >> 4) * 8;
    const int kcsB  = (lane >> 3) & 1;
    const int klane = lane & 7;

    float acc[3][12][4];
#pragma unroll
    for (int i = 0; i < 3; i++)
#pragma unroll
        for (int j = 0; j < 12; j++)
#pragma unroll
            for (int r = 0; r < 4; r++) acc[i][j][r] = 0.f;

    auto fillA = [&](int st, int y) {
        uint32_t smA = smem + st * STAGE_B;
#pragma unroll
        for (int i = 0; i < 6; i++) {
            int c  = tid + 128 * i;
            int m  = c >> 3, kc = c & 7;
            uint32_t dst = smA + m * 128 + ((kc ^ (m & 7)) << 4);
            cp_async16(dst, xAh + (size_t)m * HW_ + (y << 6) + kc * 8);
        }
    };
    auto fillB = [&](int st, int y) {
        uint32_t smB = smem + st * STAGE_B + 12288;
        int py = y + dy; if (py < 0) py = 0;
#pragma unroll
        for (int i = 0; i < 12; i++) {
            int q = i * 128 + tid;
            int n = q >> 3, kc = q & 7;
            uint32_t dst = smB + n * 128 + ((kc ^ (n & 7)) << 4);
            cp_async16(dst, xBh + (size_t)n * HW_ + (py << 6) + kc * 8);
        }
    };

    fillB(0, y0);
    fillA(0, y0);
    cp_commit();

    for (int kt = 0; kt < NKT; kt++) {
        int st = kt & 1;
        __syncthreads();
        if (kt + 1 < NKT) {
            fillB(st ^ 1, y0 + kt + 1);
            fillA(st ^ 1, y0 + kt + 1);
            cp_commit();
            cp_wait<1>();
        } else {
            cp_wait<0>();
        }
        __syncthreads();

        uint32_t smA = smem + st * STAGE_B;
        uint32_t smB = smA + 12288;
        uint32_t aA0 = smA + (wr * 48 + mrel) * 128;
        uint32_t aB0 = smB + (wc * 96 + nrel) * 128;

#pragma unroll
        for (int ks = 0; ks < 4; ks++) {
            uint32_t af[3][4], bf[6][4];
#pragma unroll
            for (int i = 0; i < 3; i++)
                ldsm4(af[i], aA0 + i * (16 * 128) + (((ks * 2 + kcsA) ^ klane) << 4));
#pragma unroll
            for (int t = 0; t < 6; t++)
                ldsm4(bf[t], aB0 + t * (16 * 128) + (((ks * 2 + kcsB) ^ klane) << 4));
#pragma unroll
            for (int i = 0; i < 3; i++)
#pragma unroll
                for (int j = 0; j < 12; j++)
                    mma16(acc[i][j], af[i], &bf[j >> 1][(j & 1) * 2]);
        }
    }

    // ---- epilogue: stage tile in smem (96x192 fp32 = 73728B), then red.v4 ----
    __syncthreads();                     // all MMAs done; smem stages reusable
    float* smf = reinterpret_cast<float*>(smraw);
    const int rA = lane >> 2, cB = (lane & 3) * 2;
#pragma unroll
    for (int i = 0; i < 3; i++) {
        int r0 = wr * 48 + i * 16 + rA;
#pragma unroll
        for (int j = 0; j < 12; j++) {
            int col = wc * 96 + j * 8 + cB;
            *reinterpret_cast<float2*>(smf + r0 * 192 + col) =
                make_float2(acc[i][j][0], acc[i][j][1]);
            *reinterpret_cast<float2*>(smf + (r0 + 8) * 192 + col) =
                make_float2(acc[i][j][2], acc[i][j][3]);
        }
    }
    __syncthreads();
    // CTA tile is a contiguous global chunk: out[g*NOUT + cA0*192 ... +18432)
    float* po = out + (size_t)g * NOUT + (size_t)cA0 * C_;
    const float4* sm4 = reinterpret_cast<const float4*>(smf);
#pragma unroll
    for (int i = 0; i < 36; i++) {
        int q = tid + 128 * i;
        red_v4(po + q * 4, sm4[q]);
    }
}

// ---------------------------------------------------------------------------
__global__ __launch_bounds__(1024) void cofe_zero(float* __restrict__ out) {
    int i = blockIdx.x * 1024 + threadIdx.x;              // 720 blocks exact
    reinterpret_cast<float4*>(out)[i] = make_float4(0.f, 0.f, 0.f, 0.f);
    if (blockIdx.x == 0 && threadIdx.x < 80) g_sums[threadIdx.x] = 0.f;
}

// norm pass 1: partial square-sums (grid 80*16)
__global__ __launch_bounds__(256) void cofe_norm1(const float* __restrict__ out) {
    const int g = blockIdx.x >> 4, seg = blockIdx.x & 15;
    const float4* p = reinterpret_cast<const float4*>(out + (size_t)g * NOUT + seg * 2304);
    const int tid = threadIdx.x;
    float ss = 0.f;
#pragma unroll
    for (int i = tid; i < 576; i += 256) {
        float4 v = p[i];
        ss += v.x * v.x + v.y * v.y + v.z * v.z + v.w * v.w;
    }
    __shared__ float red[8];
#pragma unroll
    for (int d = 16; d > 0; d >>= 1) ss += __shfl_xor_sync(0xffffffffu, ss, d);
    if ((tid & 31) == 0) red[tid >> 5] = ss;
    __syncthreads();
    if (tid < 32) {
        float v = (tid < 8) ? red[tid] : 0.f;
#pragma unroll
        for (int d = 4; d > 0; d >>= 1) v += __shfl_xor_sync(0xffffffffu, v, d);
        if (tid == 0) atomicAdd(&g_sums[g], v);
    }
}

// norm pass 2: scale (grid 80*16)
__global__ __launch_bounds__(256) void cofe_norm2(float* __restrict__ out) {
    const int g = blockIdx.x >> 4, seg = blockIdx.x & 15;
    float4* p = reinterpret_cast<float4*>(out + (size_t)g * NOUT + seg * 2304);
    const float scale = 1.0f / fmaxf(sqrtf(g_sums[g]), 1e-12f);
    const int tid = threadIdx.x;
#pragma unroll
    for (int i = tid; i < 576; i += 256) {
        float4 v = p[i];
        v.x *= scale; v.y *= scale; v.z *= scale; v.w *= scale;
        p[i] = v;
    }
}

// ---------------------------------------------------------------------------
extern "C" void kernel_launch(void* const* d_in, const int* in_sizes, int n_in,
                              void* d_out, int out_size) {
    const float* x = (const float*)d_in[0];
    float* out = (float*)d_out;

    cofe_zero<<<720, 1024>>>(out);
    cofe_prep<<<12288, 256>>>(x);
    cudaFuncSetAttribute(cofe_mma, cudaFuncAttributeMaxDynamicSharedMemorySize, SM_REQ);
    cofe_mma<<<1280, 128, SM_REQ>>>(out);
    cofe_norm1<<<1280, 256>>>(out);
    cofe_norm2<<<1280, 256>>>(out);
}

// round 7
// speedup vs baseline: 1.0378x; 1.0378x over previous
#include <cuda_runtime.h>
#include <cuda_fp16.h>
#include <cstdint>

#define B_    16
#define C_    192
#define HW_   4096
#define NOUT  (C_*C_)
#define KSPLIT 8
#define KPER   (HW_/KSPLIT)     // 512
#define NKT    (KPER/64)        // 8 k-tiles (64 k each = one image row)

__device__ float g_sums[80];
__device__ int   g_cnt[80];
// fp16 copies: variant v: 0 -> dx=-1, 1 -> dx=0, 2 -> dx=+1  (edge-clamped in x)
__device__ __half g_xh[(size_t)3 * B_ * C_ * HW_];

// ---------------------------------------------------------------------------
__device__ __forceinline__ uint32_t smem_u32(const void* p) {
    uint32_t a;
    asm("{ .reg .u64 t; cvta.to.shared.u64 t, %1; cvt.u32.u64 %0, t; }" : "=r"(a) : "l"(p));
    return a;
}
__device__ __forceinline__ void cp_async16(uint32_t dst, const void* src) {
    asm volatile("cp.async.cg.shared.global [%0], [%1], 16;" :: "r"(dst), "l"(src) : "memory");
}
__device__ __forceinline__ void cp_commit() {
    asm volatile("cp.async.commit_group;" ::: "memory");
}
template <int N>
__device__ __forceinline__ void cp_wait() {
    asm volatile("cp.async.wait_group %0;" :: "n"(N) : "memory");
}
__device__ __forceinline__ void ldsm4(uint32_t* r, uint32_t addr) {
    asm volatile("ldmatrix.sync.aligned.m8n8.x4.shared.b16 {%0,%1,%2,%3}, [%4];"
                 : "=r"(r[0]), "=r"(r[1]), "=r"(r[2]), "=r"(r[3]) : "r"(addr));
}
__device__ __forceinline__ void mma16(float* d, const uint32_t* a, const uint32_t* b) {
    asm volatile("mma.sync.aligned.m16n8k16.row.col.f32.f16.f16.f32 "
                 "{%0,%1,%2,%3}, {%4,%5,%6,%7}, {%8,%9}, {%0,%1,%2,%3};"
                 : "+f"(d[0]), "+f"(d[1]), "+f"(d[2]), "+f"(d[3])
                 : "r"(a[0]), "r"(a[1]), "r"(a[2]), "r"(a[3]), "r"(b[0]), "r"(b[1]));
}

// ---------------------------------------------------------------------------
// prep (fused with output zero-init): fp16-convert x into 3 dx-shifted
// variants; also zero out[] and the norm counters (needed per graph replay).
// ---------------------------------------------------------------------------
__global__ __launch_bounds__(256) void cofe_prep(const float* __restrict__ x,
                                                 float* __restrict__ out) {
    int idx = blockIdx.x * 256 + threadIdx.x;     // 12288 * 256 = 3,145,728
    // fused zero-init: out has 737,280 float4s
    if (idx < 737280)
        reinterpret_cast<float4*>(out)[idx] = make_float4(0.f, 0.f, 0.f, 0.f);
    if (idx < 80) { g_sums[idx] = 0.f; g_cnt[idx] = 0; }

    int row = idx >> 4;                            // (b*C + c)*64 + y
    int q   = idx & 15;
    const float* src = x + (size_t)row * 64 + q * 4;
    float4 v = *reinterpret_cast<const float4*>(src);
    float lm = (q == 0)  ? v.x : src[-1];
    float rp = (q == 15) ? v.w : src[4];

    size_t o = (size_t)row * 64 + q * 4;
    const size_t VS = (size_t)B_ * C_ * HW_;
    __half2* d0 = reinterpret_cast<__half2*>(g_xh + o);            // dx=-1
    __half2* d1 = reinterpret_cast<__half2*>(g_xh + VS + o);       // dx=0
    __half2* d2 = reinterpret_cast<__half2*>(g_xh + 2 * VS + o);   // dx=+1
    d0[0] = __floats2half2_rn(lm,  v.x); d0[1] = __floats2half2_rn(v.y, v.z);
    d1[0] = __floats2half2_rn(v.x, v.y); d1[1] = __floats2half2_rn(v.z, v.w);
    d2[0] = __floats2half2_rn(v.y, v.z); d2[1] = __floats2half2_rn(v.w, rp);
}

// ---------------------------------------------------------------------------
// GEMM: CTA tile M=96, N=192, K=512 (one split), fp16 HMMA m16n8k16.
// 128 threads = 4 warps (2x2), warp tile 48x96, k-tile 64 (=128B rows fp16).
// Epilogue: scalar atomicAdd into out[g] (overlaps with other waves).
// ---------------------------------------------------------------------------
#define STAGE_B 36864
#define SM_REQ  (2 * STAGE_B)

__global__ __launch_bounds__(128, 2)
void cofe_mma(float* __restrict__ out) {
    extern __shared__ char smraw[];
    const uint32_t smem = smem_u32(smraw);

    const int tid  = threadIdx.x;
    const int lane = tid & 31;
    const int wid  = tid >> 5;
    const int wr   = wid >> 1;
    const int wc   = wid & 1;

    const int bx  = blockIdx.x;
    const int s   = bx & 7;             // k-split
    const int mt  = (bx >> 3) & 1;      // M tile
    const int g   = bx >> 4;            // 0..79
    const int b   = g / 5, off = g % 5;
    const int dy  = (off < 3) ? -1 : 0;
    const int dx  = (off < 3) ? (off - 1) : ((off == 3) ? -1 : 0);

    const int cA0 = mt * 96;
    const int y0  = s * (KPER / 64);
    const size_t VS = (size_t)B_ * C_ * HW_;
    const __half* xAh = g_xh + VS + ((size_t)(b * C_ + cA0)) * HW_;      // dx=0
    const __half* xBh = g_xh + (size_t)(dx + 1) * VS + (size_t)(b * C_) * HW_;

    const int mrel  = (lane & 7) + ((lane >> 3) & 1) * 8;
    const int kcsA  = lane >> 4;
    const int nrel  = (lane & 7) + (lane >> 4) * 8;
    const int kcsB  = (lane >> 3) & 1;
    const int klane = lane & 7;

    float acc[3][12][4];
#pragma unroll
    for (int i = 0; i < 3; i++)
#pragma unroll
        for (int j = 0; j < 12; j++)
#pragma unroll
            for (int r = 0; r < 4; r++) acc[i][j][r] = 0.f;

    auto fillA = [&](int st, int y) {
        uint32_t smA = smem + st * STAGE_B;
#pragma unroll
        for (int i = 0; i < 6; i++) {
            int c  = tid + 128 * i;
            int m  = c >> 3, kc = c & 7;
            uint32_t dst = smA + m * 128 + ((kc ^ (m & 7)) << 4);
            cp_async16(dst, xAh + (size_t)m * HW_ + (y << 6) + kc * 8);
        }
    };
    auto fillB = [&](int st, int y) {
        uint32_t smB = smem + st * STAGE_B + 12288;
        int py = y + dy; if (py < 0) py = 0;
#pragma unroll
        for (int i = 0; i < 12; i++) {
            int q = i * 128 + tid;
            int n = q >> 3, kc = q & 7;
            uint32_t dst = smB + n * 128 + ((kc ^ (n & 7)) << 4);
            cp_async16(dst, xBh + (size_t)n * HW_ + (py << 6) + kc * 8);
        }
    };

    fillB(0, y0);
    fillA(0, y0);
    cp_commit();

    for (int kt = 0; kt < NKT; kt++) {
        int st = kt & 1;
        __syncthreads();
        if (kt + 1 < NKT) {
            fillB(st ^ 1, y0 + kt + 1);
            fillA(st ^ 1, y0 + kt + 1);
            cp_commit();
            cp_wait<1>();
        } else {
            cp_wait<0>();
        }
        __syncthreads();

        uint32_t smA = smem + st * STAGE_B;
        uint32_t smB = smA + 12288;
        uint32_t aA0 = smA + (wr * 48 + mrel) * 128;
        uint32_t aB0 = smB + (wc * 96 + nrel) * 128;

#pragma unroll
        for (int ks = 0; ks < 4; ks++) {
            uint32_t af[3][4], bf[6][4];
#pragma unroll
            for (int i = 0; i < 3; i++)
                ldsm4(af[i], aA0 + i * (16 * 128) + (((ks * 2 + kcsA) ^ klane) << 4));
#pragma unroll
            for (int t = 0; t < 6; t++)
                ldsm4(bf[t], aB0 + t * (16 * 128) + (((ks * 2 + kcsB) ^ klane) << 4));
#pragma unroll
            for (int i = 0; i < 3; i++)
#pragma unroll
                for (int j = 0; j < 12; j++)
                    mma16(acc[i][j], af[i], &bf[j >> 1][(j & 1) * 2]);
        }
    }

    // ---- epilogue: RED into out[g] ----
    float* po = out + (size_t)g * NOUT;
    const int rA = lane >> 2, cB = (lane & 3) * 2;
#pragma unroll
    for (int i = 0; i < 3; i++) {
        int c0 = cA0 + wr * 48 + i * 16 + rA;
#pragma unroll
        for (int j = 0; j < 12; j++) {
            int d0 = wc * 96 + j * 8 + cB;
            atomicAdd(po + (size_t)c0 * C_ + d0,     acc[i][j][0]);
            atomicAdd(po + (size_t)c0 * C_ + d0 + 1, acc[i][j][1]);
            atomicAdd(po + (size_t)(c0 + 8) * C_ + d0,     acc[i][j][2]);
            atomicAdd(po + (size_t)(c0 + 8) * C_ + d0 + 1, acc[i][j][3]);
        }
    }
}

// ---------------------------------------------------------------------------
// fused norm: 8 blocks per g (grid 640, all resident -> spin barrier safe).
// pass1 partial ss -> atomicAdd; arrival count; spin to 8; scale own segment.
// ---------------------------------------------------------------------------
__global__ __launch_bounds__(256) void cofe_norm(float* __restrict__ out) {
    const int g = blockIdx.x >> 3, seg = blockIdx.x & 7;
    float4* p = reinterpret_cast<float4*>(out + (size_t)g * NOUT + seg * 4608);
    const int tid = threadIdx.x;

    float ss = 0.f;
#pragma unroll
    for (int i = tid; i < 1152; i += 256) {
        float4 v = p[i];
        ss += v.x * v.x + v.y * v.y + v.z * v.z + v.w * v.w;
    }
    __shared__ float red[8];
    __shared__ float s_scale;
#pragma unroll
    for (int d = 16; d > 0; d >>= 1) ss += __shfl_xor_sync(0xffffffffu, ss, d);
    if ((tid & 31) == 0) red[tid >> 5] = ss;
    __syncthreads();
    if (tid == 0) {
        float v = red[0] + red[1] + red[2] + red[3] +
                  red[4] + red[5] + red[6] + red[7];
        atomicAdd(&g_sums[g], v);
        __threadfence();
        atomicAdd(&g_cnt[g], 1);
        while (atomicAdd(&g_cnt[g], 0) < 8) { }
        __threadfence();
        float tot = atomicAdd(&g_sums[g], 0.0f);
        s_scale = 1.0f / fmaxf(sqrtf(tot), 1e-12f);
    }
    __syncthreads();
    const float scale = s_scale;

#pragma unroll
    for (int i = tid; i < 1152; i += 256) {
        float4 v = p[i];
        v.x *= scale; v.y *= scale; v.z *= scale; v.w *= scale;
        p[i] = v;
    }
}

// ---------------------------------------------------------------------------
extern "C" void kernel_launch(void* const* d_in, const int* in_sizes, int n_in,
                              void* d_out, int out_size) {
    const float* x = (const float*)d_in[0];
    float* out = (float*)d_out;

    cofe_prep<<<12288, 256>>>(x, out);
    cudaFuncSetAttribute(cofe_mma, cudaFuncAttributeMaxDynamicSharedMemorySize, SM_REQ);
    cofe_mma<<<1280, 128, SM_REQ>>>(out);
    cofe_norm<<<640, 256>>>(out);
}